// round 1
// baseline (speedup 1.0000x reference)
#include <cuda_runtime.h>
#include <cstdint>

#define N_PTS 20000
#define N_PAD 20032          // padded to multiple of 64 for the KNN tile loop
#define E_EDG 320000
#define NTILES 313           // 313*64 = 20032

// ---------------- device scratch (no allocations allowed) ----------------
__device__ float g_x1[N_PAD * 64];        // node features after stage 1 (padded rows = 0)
__device__ float g_sq[N_PAD];             // squared norms (pad = 1e30 -> never selected)
__device__ int   g_nbr[N_PTS * 16];       // knn indices
__device__ float g_x2[N_PTS * 64];        // stage-2 features
__device__ float g_xs[N_PTS * 4 * 64];    // xe reshaped/transposed rows
__device__ float g_feat[N_PTS * 4 * 64];  // feat = xs@Wp+bp

// ---------------- zero x1 (incl. pad rows) ----------------
__global__ void k_zero() {
    int i = blockIdx.x * blockDim.x + threadIdx.x;   // 1252*256 == N_PAD*64/4 exactly
    ((float4*)g_x1)[i] = make_float4(0.f, 0.f, 0.f, 0.f);
}

// ---------------- stage 1: edge MLP (6->64 relu ->64 relu) + segment max ----------------
__global__ void __launch_bounds__(256) k_edge(const float* __restrict__ dep,
                                              const int*   __restrict__ ei,
                                              const float* __restrict__ W1a,
                                              const float* __restrict__ b1a,
                                              const float* __restrict__ W1b,
                                              const float* __restrict__ b1b) {
    __shared__ float sW1a[6 * 64];
    __shared__ float sW1b[64 * 64];
    __shared__ float sb1a[64];
    __shared__ float sb1b[64];
    int tid = threadIdx.x;
    for (int m = tid; m < 6 * 64; m += 256) sW1a[m] = W1a[m];
    for (int m = tid; m < 64 * 64; m += 256) sW1b[m] = W1b[m];
    if (tid < 64) { sb1a[tid] = b1a[tid]; sb1b[tid] = b1b[tid]; }
    __syncthreads();

    int e = blockIdx.x * 256 + tid;                 // grid 1250*256 == E exactly
    int s = ei[e];
    int d = ei[E_EDG + e];
    float xi0 = dep[d * 3], xi1 = dep[d * 3 + 1], xi2 = dep[d * 3 + 2];
    float in6[6];
    in6[0] = xi0; in6[1] = xi1; in6[2] = xi2;
    in6[3] = dep[s * 3] - xi0; in6[4] = dep[s * 3 + 1] - xi1; in6[5] = dep[s * 3 + 2] - xi2;

    float h[64];
#pragma unroll
    for (int f = 0; f < 64; f++) h[f] = sb1a[f];
#pragma unroll
    for (int k = 0; k < 6; k++) {
        float v = in6[k];
#pragma unroll
        for (int f4 = 0; f4 < 16; f4++) {
            float4 w = ((const float4*)sW1a)[k * 16 + f4];
            h[f4 * 4 + 0] += v * w.x; h[f4 * 4 + 1] += v * w.y;
            h[f4 * 4 + 2] += v * w.z; h[f4 * 4 + 3] += v * w.w;
        }
    }
#pragma unroll
    for (int f = 0; f < 64; f++) h[f] = fmaxf(h[f], 0.f);

    int* outp = (int*)(g_x1 + (size_t)d * 64);
    for (int c = 0; c < 4; c++) {                   // 16-wide output chunks
        float o[16];
#pragma unroll
        for (int m = 0; m < 16; m++) o[m] = sb1b[c * 16 + m];
#pragma unroll
        for (int k = 0; k < 64; k++) {
            float hk = h[k];
#pragma unroll
            for (int q = 0; q < 4; q++) {
                float4 w = ((const float4*)sW1b)[k * 16 + c * 4 + q];
                o[q * 4 + 0] += hk * w.x; o[q * 4 + 1] += hk * w.y;
                o[q * 4 + 2] += hk * w.z; o[q * 4 + 3] += hk * w.w;
            }
        }
#pragma unroll
        for (int m = 0; m < 16; m++) {
            float v = fmaxf(o[m], 0.f);             // relu => v >= 0 => int-compare valid
            atomicMax(outp + c * 16 + m, __float_as_int(v));
        }
    }
}

// ---------------- squared norms ----------------
__global__ void k_sq() {
    int i = blockIdx.x * blockDim.x + threadIdx.x;
    if (i >= N_PAD) return;
    if (i >= N_PTS) { g_sq[i] = 1e30f; return; }    // pad rows unreachable by knn
    const float4* p = (const float4*)(g_x1 + (size_t)i * 64);
    float s = 0.f;
#pragma unroll
    for (int k = 0; k < 16; k++) { float4 v = p[k]; s += v.x * v.x + v.y * v.y + v.z * v.z + v.w * v.w; }
    g_sq[i] = s;
}

// ---------------- KNN: per-row top-16 smallest d2 over all 20000 points ----------------
__global__ void __launch_bounds__(128) k_knn() {
    __shared__ float4 ftile[64 * 16];   // 64 key rows x 64 feats
    __shared__ float  ssq[64];
    __shared__ float  cd[128 * 16];     // candidate merge buffers
    __shared__ int    ci[128 * 16];

    int tid   = threadIdx.x;
    int row   = tid & 63;
    int phase = tid >> 6;               // 0: even j within tile, 1: odd j
    int gi    = blockIdx.x * 64 + row;  // < N_PAD always (313*64 == 20032)

    float fi[64];
    const float4* fp = (const float4*)(g_x1 + (size_t)gi * 64);
#pragma unroll
    for (int k4 = 0; k4 < 16; k4++) {
        float4 v = fp[k4];
        fi[k4 * 4 + 0] = v.x; fi[k4 * 4 + 1] = v.y; fi[k4 * 4 + 2] = v.z; fi[k4 * 4 + 3] = v.w;
    }
    float sqi = g_sq[gi];

    float best[16]; int bidx[16];
#pragma unroll
    for (int m = 0; m < 16; m++) { best[m] = 3.0e38f; bidx[m] = 0x7FFFFFFF; }
    float worst = 3.0e38f;

    for (int t = 0; t < NTILES; t++) {
        int base = t * 64;
        __syncthreads();
#pragma unroll
        for (int m = 0; m < 8; m++) {
            int lin = m * 128 + tid;    // 1024 float4 per tile
            ftile[lin] = ((const float4*)g_x1)[base * 16 + lin];
        }
        if (tid < 64) ssq[tid] = g_sq[base + tid];
        __syncthreads();

        for (int jj = phase; jj < 64; jj += 2) {
            float a0 = 0.f, a1 = 0.f, a2 = 0.f, a3 = 0.f;
#pragma unroll
            for (int k4 = 0; k4 < 16; k4++) {
                float4 v = ftile[jj * 16 + k4];
                a0 += fi[k4 * 4 + 0] * v.x; a1 += fi[k4 * 4 + 1] * v.y;
                a2 += fi[k4 * 4 + 2] * v.z; a3 += fi[k4 * 4 + 3] * v.w;
            }
            float d2 = sqi + ssq[jj] - 2.f * ((a0 + a1) + (a2 + a3));
            int j = base + jj;
            if (d2 < worst) {           // strict '<' : ascending j keeps smaller index on ties
                float mv = best[0]; int mi = bidx[0]; int slot = 0;
#pragma unroll
                for (int m = 1; m < 16; m++) {
                    bool g = (best[m] > mv) || (best[m] == mv && bidx[m] > mi);
                    if (g) { mv = best[m]; mi = bidx[m]; slot = m; }
                }
#pragma unroll
                for (int m = 0; m < 16; m++) if (m == slot) { best[m] = d2; bidx[m] = j; }
                float w = best[0];
#pragma unroll
                for (int m = 1; m < 16; m++) w = fmaxf(w, best[m]);
                worst = w;
            }
        }
    }

#pragma unroll
    for (int m = 0; m < 16; m++) { cd[tid * 16 + m] = best[m]; ci[tid * 16 + m] = bidx[m]; }
    __syncthreads();

    if (phase == 0 && gi < N_PTS) {     // merge the two parity lists (lexicographic tiebreak)
        for (int sel = 0; sel < 16; sel++) {
            float mv = 3.4e38f; int mi = 0x7FFFFFFF; int ms = 0;
            for (int m = 0; m < 32; m++) {
                int idx = ((m < 16) ? tid : (tid + 64)) * 16 + (m & 15);
                float v = cd[idx]; int ix = ci[idx];
                if (v < mv || (v == mv && ix < mi)) { mv = v; mi = ix; ms = idx; }
            }
            g_nbr[gi * 16 + sel] = mi;
            cd[ms] = 3.4e38f;
        }
    }
}

// ---------------- stage 2: edgeconv (128->64 relu ->64 relu), max over 16 neighbors ----------------
__global__ void __launch_bounds__(128) k_conv2(const float* __restrict__ W2a,
                                               const float* __restrict__ b2a,
                                               const float* __restrict__ W2b,
                                               const float* __restrict__ b2b) {
    __shared__ float sW2a[128 * 64];    // 32 KB
    __shared__ float sW2b[64 * 64];     // 16 KB  (total 48KB exactly; biases via __ldg)
    int tid = threadIdx.x;
    for (int m = tid; m < 128 * 64; m += 128) sW2a[m] = W2a[m];
    for (int m = tid; m < 64 * 64;  m += 128) sW2b[m] = W2b[m];
    __syncthreads();

    int gid = blockIdx.x * 128 + tid;   // 2500*128 == 320000 exactly
    int i  = gid >> 4;
    int jn = gid & 15;
    int j  = g_nbr[i * 16 + jn];
    const float4* xi4 = (const float4*)(g_x1 + (size_t)i * 64);
    const float4* xj4 = (const float4*)(g_x1 + (size_t)j * 64);

    float h[64];
#pragma unroll
    for (int f = 0; f < 64; f++) h[f] = __ldg(&b2a[f]);

#pragma unroll 4
    for (int k4 = 0; k4 < 16; k4++) {
        float4 A = xi4[k4], B = xj4[k4];
        float av[4] = {A.x, A.y, A.z, A.w};
        float dv[4] = {B.x - A.x, B.y - A.y, B.z - A.z, B.w - A.w};
#pragma unroll
        for (int s = 0; s < 4; s++) {
            int k = k4 * 4 + s;
            float a = av[s], dd = dv[s];
#pragma unroll
            for (int f4 = 0; f4 < 16; f4++) {
                float4 w1 = ((const float4*)sW2a)[k * 16 + f4];
                float4 w2 = ((const float4*)sW2a)[(64 + k) * 16 + f4];
                h[f4 * 4 + 0] += a * w1.x + dd * w2.x;
                h[f4 * 4 + 1] += a * w1.y + dd * w2.y;
                h[f4 * 4 + 2] += a * w1.z + dd * w2.z;
                h[f4 * 4 + 3] += a * w1.w + dd * w2.w;
            }
        }
    }
#pragma unroll
    for (int f = 0; f < 64; f++) h[f] = fmaxf(h[f], 0.f);

    for (int c = 0; c < 4; c++) {
        float o[16];
#pragma unroll
        for (int m = 0; m < 16; m++) o[m] = __ldg(&b2b[c * 16 + m]);
#pragma unroll
        for (int k = 0; k < 64; k++) {
            float hk = h[k];
#pragma unroll
            for (int q = 0; q < 4; q++) {
                float4 w = ((const float4*)sW2b)[k * 16 + c * 4 + q];
                o[q * 4 + 0] += hk * w.x; o[q * 4 + 1] += hk * w.y;
                o[q * 4 + 2] += hk * w.z; o[q * 4 + 3] += hk * w.w;
            }
        }
#pragma unroll
        for (int m = 0; m < 16; m++) {
            float v = fmaxf(o[m], 0.f);                              // relu before max
            v = fmaxf(v, __shfl_xor_sync(0xFFFFFFFFu, v, 1, 16));    // max over 16 neighbors
            v = fmaxf(v, __shfl_xor_sync(0xFFFFFFFFu, v, 2, 16));
            v = fmaxf(v, __shfl_xor_sync(0xFFFFFFFFu, v, 4, 16));
            v = fmaxf(v, __shfl_xor_sync(0xFFFFFFFFu, v, 8, 16));
            o[m] = v;
        }
        if (jn == 0) {
            float4* dst = (float4*)(g_x2 + (size_t)i * 64 + c * 16);
            dst[0] = make_float4(o[0],  o[1],  o[2],  o[3]);
            dst[1] = make_float4(o[4],  o[5],  o[6],  o[7]);
            dst[2] = make_float4(o[8],  o[9],  o[10], o[11]);
            dst[3] = make_float4(o[12], o[13], o[14], o[15]);
        }
    }
}

// ---------------- xe = x2 @ We + be, transposed-store per (i, r) ----------------
__global__ void __launch_bounds__(256) k_lin1(const float* __restrict__ We,
                                              const float* __restrict__ be) {
    __shared__ float sW[64 * 64];
    __shared__ float sb[64];
    int r = blockIdx.y, tid = threadIdx.x;
    for (int m = tid; m < 4096; m += 256) {
        int k = m >> 6, c = m & 63;
        sW[m] = We[k * 256 + r * 64 + c];
    }
    if (tid < 64) sb[tid] = be[r * 64 + tid];
    __syncthreads();

    int i = blockIdx.x * 256 + tid;
    if (i >= N_PTS) return;
    float x[64];
    const float4* xp = (const float4*)(g_x2 + (size_t)i * 64);
#pragma unroll
    for (int k4 = 0; k4 < 16; k4++) {
        float4 v = xp[k4];
        x[k4 * 4 + 0] = v.x; x[k4 * 4 + 1] = v.y; x[k4 * 4 + 2] = v.z; x[k4 * 4 + 3] = v.w;
    }
    float* outp = g_xs + ((size_t)r * N_PTS + i) * 64;
    for (int c = 0; c < 4; c++) {
        float o[16];
#pragma unroll
        for (int m = 0; m < 16; m++) o[m] = sb[c * 16 + m];
#pragma unroll
        for (int k = 0; k < 64; k++) {
            float xk = x[k];
#pragma unroll
            for (int q = 0; q < 4; q++) {
                float4 w = ((const float4*)sW)[k * 16 + c * 4 + q];
                o[q * 4 + 0] += xk * w.x; o[q * 4 + 1] += xk * w.y;
                o[q * 4 + 2] += xk * w.z; o[q * 4 + 3] += xk * w.w;
            }
        }
        float4* op = (float4*)(outp + c * 16);
        op[0] = make_float4(o[0],  o[1],  o[2],  o[3]);
        op[1] = make_float4(o[4],  o[5],  o[6],  o[7]);
        op[2] = make_float4(o[8],  o[9],  o[10], o[11]);
        op[3] = make_float4(o[12], o[13], o[14], o[15]);
    }
}

// ---------------- feat = xs @ Wp + bp ----------------
__global__ void __launch_bounds__(256) k_feat(const float* __restrict__ Wp,
                                              const float* __restrict__ bp) {
    __shared__ float sW[64 * 64];
    __shared__ float sb[64];
    int tid = threadIdx.x;
    for (int m = tid; m < 4096; m += 256) sW[m] = Wp[m];
    if (tid < 64) sb[tid] = bp[tid];
    __syncthreads();
    int i = blockIdx.x * 256 + tid;
    if (i >= N_PTS * 4) return;
    float x[64];
    const float4* xp = (const float4*)(g_xs + (size_t)i * 64);
#pragma unroll
    for (int k4 = 0; k4 < 16; k4++) {
        float4 v = xp[k4];
        x[k4 * 4 + 0] = v.x; x[k4 * 4 + 1] = v.y; x[k4 * 4 + 2] = v.z; x[k4 * 4 + 3] = v.w;
    }
    float* outp = g_feat + (size_t)i * 64;
    for (int c = 0; c < 4; c++) {
        float o[16];
#pragma unroll
        for (int m = 0; m < 16; m++) o[m] = sb[c * 16 + m];
#pragma unroll
        for (int k = 0; k < 64; k++) {
            float xk = x[k];
#pragma unroll
            for (int q = 0; q < 4; q++) {
                float4 w = ((const float4*)sW)[k * 16 + c * 4 + q];
                o[q * 4 + 0] += xk * w.x; o[q * 4 + 1] += xk * w.y;
                o[q * 4 + 2] += xk * w.z; o[q * 4 + 3] += xk * w.w;
            }
        }
        float4* op = (float4*)(outp + c * 16);
        op[0] = make_float4(o[0],  o[1],  o[2],  o[3]);
        op[1] = make_float4(o[4],  o[5],  o[6],  o[7]);
        op[2] = make_float4(o[8],  o[9],  o[10], o[11]);
        op[3] = make_float4(o[12], o[13], o[14], o[15]);
    }
}

// ---------------- head: h = relu(feat@Wr1+br1); out = h@Wr2 + br2 ----------------
__global__ void __launch_bounds__(256) k_head(float* __restrict__ out,
                                              const float* __restrict__ Wr1,
                                              const float* __restrict__ br1,
                                              const float* __restrict__ Wr2,
                                              const float* __restrict__ br2) {
    __shared__ float sW[64 * 64];
    __shared__ float sb[64];
    __shared__ float sW2[64 * 3];
    __shared__ float sb2[3];
    int tid = threadIdx.x;
    for (int m = tid; m < 4096; m += 256) sW[m] = Wr1[m];
    if (tid < 64) sb[tid] = br1[tid];
    if (tid < 192) sW2[tid] = Wr2[tid];
    if (tid < 3) sb2[tid] = br2[tid];
    __syncthreads();
    int i = blockIdx.x * 256 + tid;
    if (i >= N_PTS * 4) return;
    float x[64];
    const float4* xp = (const float4*)(g_feat + (size_t)i * 64);
#pragma unroll
    for (int k4 = 0; k4 < 16; k4++) {
        float4 v = xp[k4];
        x[k4 * 4 + 0] = v.x; x[k4 * 4 + 1] = v.y; x[k4 * 4 + 2] = v.z; x[k4 * 4 + 3] = v.w;
    }
    float o0 = sb2[0], o1 = sb2[1], o2 = sb2[2];
    for (int c = 0; c < 4; c++) {
        float o[16];
#pragma unroll
        for (int m = 0; m < 16; m++) o[m] = sb[c * 16 + m];
#pragma unroll
        for (int k = 0; k < 64; k++) {
            float xk = x[k];
#pragma unroll
            for (int q = 0; q < 4; q++) {
                float4 w = ((const float4*)sW)[k * 16 + c * 4 + q];
                o[q * 4 + 0] += xk * w.x; o[q * 4 + 1] += xk * w.y;
                o[q * 4 + 2] += xk * w.z; o[q * 4 + 3] += xk * w.w;
            }
        }
#pragma unroll
        for (int m = 0; m < 16; m++) {
            float hm = fmaxf(o[m], 0.f);
            int jrow = c * 16 + m;
            o0 += hm * sW2[jrow * 3 + 0];
            o1 += hm * sW2[jrow * 3 + 1];
            o2 += hm * sW2[jrow * 3 + 2];
        }
    }
    out[(size_t)i * 3 + 0] = o0;
    out[(size_t)i * 3 + 1] = o1;
    out[(size_t)i * 3 + 2] = o2;
}

// ---------------- launch ----------------
extern "C" void kernel_launch(void* const* d_in, const int* in_sizes, int n_in,
                              void* d_out, int out_size) {
    const float* dep = (const float*)d_in[0];
    const float* W1a = (const float*)d_in[1];
    const float* b1a = (const float*)d_in[2];
    const float* W1b = (const float*)d_in[3];
    const float* b1b = (const float*)d_in[4];
    const float* W2a = (const float*)d_in[5];
    const float* b2a = (const float*)d_in[6];
    const float* W2b = (const float*)d_in[7];
    const float* b2b = (const float*)d_in[8];
    const float* We  = (const float*)d_in[9];
    const float* be  = (const float*)d_in[10];
    const float* Wp  = (const float*)d_in[11];
    const float* bp  = (const float*)d_in[12];
    const float* Wr1 = (const float*)d_in[13];
    const float* br1 = (const float*)d_in[14];
    const float* Wr2 = (const float*)d_in[15];
    const float* br2 = (const float*)d_in[16];
    const int*   ei  = (const int*)d_in[17];
    float* out = (float*)d_out;

    k_zero<<<1252, 256>>>();                               // N_PAD*64/4 threads exactly
    k_edge<<<1250, 256>>>(dep, ei, W1a, b1a, W1b, b1b);    // E threads exactly
    k_sq<<<(N_PAD + 255) / 256, 256>>>();
    k_knn<<<NTILES, 128>>>();                              // 64 rows/block, 2 threads/row
    k_conv2<<<2500, 128>>>(W2a, b2a, W2b, b2b);            // N*16 threads exactly
    k_lin1<<<dim3((N_PTS + 255) / 256, 4), 256>>>(We, be);
    k_feat<<<(N_PTS * 4 + 255) / 256, 256>>>(Wp, bp);
    k_head<<<(N_PTS * 4 + 255) / 256, 256>>>(out, Wr1, br1, Wr2, br2);
    (void)in_sizes; (void)n_in; (void)out_size;
}